// round 1
// baseline (speedup 1.0000x reference)
#include <cuda_runtime.h>
#include <math.h>

// Problem dims
#define NB 4096   // batch
#define TT 128    // seq len
#define KV 64     // vocab
#define EE 35     // embed dim
#define LL 200    // latent dim
#define G3 600    // 3*LL
#define GE3 105   // 3*EE
#define LE 235    // LL+EE

#define NTH 800   // threads per CTA (25 warps): 100 j-groups x 8 b-groups
#define BBLK 32   // batch rows per CTA
#define NCTA (NB / BBLK)  // 128

// Output layout: concat(pred[B,T,K], mu[B,L], logvar[B,L], predY[B,1])
#define PRED_OFF ((size_t)0)
#define MU_OFF   ((size_t)NB * TT * KV)            // 33554432
#define LV_OFF   (MU_OFF + (size_t)NB * LL)        // 34373632
#define PY_OFF   (LV_OFF + (size_t)NB * LL)        // 35192832

// SMEM arena offsets (in floats); all float4-load bases are 16B aligned
#define OFF_EMB 0                    // 2240  (KV*EE)
#define OFF_H1  2240                 // 6400  (LL*32)
#define OFF_H2  8640                 // 6400
#define OFF_XE  15040                // 1120  (EE*32) ; also decoder lastword
#define OFF_ZS  16160                // 6400  (LL*32) latent z
#define OFF_MU  22560                // 6400  mu scratch
#define OFF_GZ  28960                // 3360  (GE3*32) z-part of decoder gi (const over t)
#define OFF_G1  32320                // 3360  decoder gate scratch
#define OFF_HD  35680                // 1120  decoder h1
#define SMEM_FLOATS 36800            // 147200 bytes

__device__ __forceinline__ float sigm(float v) { return 1.0f / (1.0f + expf(-v)); }

extern "C" __global__ void __launch_bounds__(NTH, 1)
vae_all(const int* __restrict__ x, const float* __restrict__ emb,
        const float* __restrict__ eW_ih0, const float* __restrict__ eW_hh0,
        const float* __restrict__ eb_ih0, const float* __restrict__ eb_hh0,
        const float* __restrict__ eW_ih1, const float* __restrict__ eW_hh1,
        const float* __restrict__ eb_ih1, const float* __restrict__ eb_hh1,
        const float* __restrict__ dW_ih0, const float* __restrict__ db_ih0,
        const float* __restrict__ db_hh0,
        const float* __restrict__ dW_ih1, const float* __restrict__ db_ih1,
        const float* __restrict__ db_hh1,
        const float* __restrict__ fc11_w, const float* __restrict__ fc11_b,
        const float* __restrict__ fc12_w, const float* __restrict__ fc12_b,
        const float* __restrict__ p1_w,  const float* __restrict__ p1_b,
        const float* __restrict__ p2_w,  const float* __restrict__ p2_b,
        const float* __restrict__ fc2_w, const float* __restrict__ fc2_b,
        const float* __restrict__ eps,   float* __restrict__ out)
{
    extern __shared__ float sm[];
    float* emb_s = sm + OFF_EMB;
    float* h1s   = sm + OFF_H1;
    float* h2s   = sm + OFF_H2;
    float* xes   = sm + OFF_XE;   // [EE][32]
    float* zs    = sm + OFF_ZS;   // [LL][32]
    float* mus   = sm + OFF_MU;   // [LL][32]
    float* gzs   = sm + OFF_GZ;   // [GE3][32]
    float* g1s   = sm + OFF_G1;   // [GE3][32]
    float* hds   = sm + OFF_HD;   // [EE][32]

    const int tid = threadIdx.x;
    const int bg0 = blockIdx.x * BBLK;

    // --- init: stage embedding table, zero hidden states ---
    for (int i = tid; i < KV * EE; i += NTH) emb_s[i] = emb[i];
    for (int i = tid; i < LL * 32; i += NTH) { h1s[i] = 0.0f; h2s[i] = 0.0f; }
    __syncthreads();

    const int jt = tid >> 3;     // 0..99
    const int bt = tid & 7;      // 0..7
    const int j0 = jt * 2;       // 0..198 (Tj=2 over LL=200)
    const int b0 = bt * 4;       // 0..28  (Tb=4 over 32)

    // =====================  ENCODER (2-layer GRU over T)  =====================
    for (int t = 0; t < TT; t++) {
        // gather embedded tokens: xes[k][b]
        for (int i = tid; i < EE * 32; i += NTH) {
            int k = i >> 5, b = i & 31;
            int tok = x[(size_t)(bg0 + b) * TT + t];
            xes[k * 32 + b] = emb_s[tok * EE + k];
        }
        __syncthreads();

        // ---------------- layer 0 ----------------
        float ar[2][4], az[2][4], an[2][4], ah[2][4];
        #pragma unroll
        for (int jj = 0; jj < 2; jj++) {
            int j = j0 + jj;
            float br = eb_ih0[j] + eb_hh0[j];
            float bz = eb_ih0[200 + j] + eb_hh0[200 + j];
            float bn = eb_ih0[400 + j];
            float bh = eb_hh0[400 + j];
            #pragma unroll
            for (int bb = 0; bb < 4; bb++) { ar[jj][bb] = br; az[jj][bb] = bz; an[jj][bb] = bn; ah[jj][bb] = bh; }
        }
        {   // x-part (K = 35, scalar weight loads)
            const float* wr = eW_ih0 + j0 * EE;
            const float* wz = eW_ih0 + (200 + j0) * EE;
            const float* wn = eW_ih0 + (400 + j0) * EE;
            #pragma unroll 1
            for (int k = 0; k < EE; k++) {
                float4 u = *(const float4*)(xes + k * 32 + b0);
                float v[4] = {u.x, u.y, u.z, u.w};
                #pragma unroll
                for (int jj = 0; jj < 2; jj++) {
                    float a = wr[jj * EE + k], c = wz[jj * EE + k], d = wn[jj * EE + k];
                    #pragma unroll
                    for (int bb = 0; bb < 4; bb++) {
                        ar[jj][bb] = fmaf(a, v[bb], ar[jj][bb]);
                        az[jj][bb] = fmaf(c, v[bb], az[jj][bb]);
                        an[jj][bb] = fmaf(d, v[bb], an[jj][bb]);
                    }
                }
            }
        }
        {   // h-part (K = 200, float2 weights, k-unroll 2)
            const float* wr = eW_hh0 + j0 * LL;
            const float* wz = eW_hh0 + (200 + j0) * LL;
            const float* wn = eW_hh0 + (400 + j0) * LL;
            #pragma unroll 1
            for (int k = 0; k < LL; k += 2) {
                float4 u = *(const float4*)(h1s + k * 32 + b0);
                float4 w = *(const float4*)(h1s + (k + 1) * 32 + b0);
                float va[4] = {u.x, u.y, u.z, u.w};
                float vb[4] = {w.x, w.y, w.z, w.w};
                #pragma unroll
                for (int jj = 0; jj < 2; jj++) {
                    float2 a = *(const float2*)(wr + jj * LL + k);
                    float2 c = *(const float2*)(wz + jj * LL + k);
                    float2 d = *(const float2*)(wn + jj * LL + k);
                    #pragma unroll
                    for (int bb = 0; bb < 4; bb++) {
                        ar[jj][bb] = fmaf(a.x, va[bb], ar[jj][bb]);
                        ar[jj][bb] = fmaf(a.y, vb[bb], ar[jj][bb]);
                        az[jj][bb] = fmaf(c.x, va[bb], az[jj][bb]);
                        az[jj][bb] = fmaf(c.y, vb[bb], az[jj][bb]);
                        ah[jj][bb] = fmaf(d.x, va[bb], ah[jj][bb]);
                        ah[jj][bb] = fmaf(d.y, vb[bb], ah[jj][bb]);
                    }
                }
            }
        }
        __syncthreads();
        #pragma unroll
        for (int jj = 0; jj < 2; jj++)
            #pragma unroll
            for (int bb = 0; bb < 4; bb++) {
                int idx = (j0 + jj) * 32 + b0 + bb;
                float ho = h1s[idx];
                float r  = sigm(ar[jj][bb]);
                float zg = sigm(az[jj][bb]);
                float n  = tanhf(fmaf(r, ah[jj][bb], an[jj][bb]));
                h1s[idx] = (1.0f - zg) * n + zg * ho;
            }
        __syncthreads();

        // ---------------- layer 1 ----------------
        #pragma unroll
        for (int jj = 0; jj < 2; jj++) {
            int j = j0 + jj;
            float br = eb_ih1[j] + eb_hh1[j];
            float bz = eb_ih1[200 + j] + eb_hh1[200 + j];
            float bn = eb_ih1[400 + j];
            float bh = eb_hh1[400 + j];
            #pragma unroll
            for (int bb = 0; bb < 4; bb++) { ar[jj][bb] = br; az[jj][bb] = bz; an[jj][bb] = bn; ah[jj][bb] = bh; }
        }
        {   // ih part over h1 (r, z, n_input)
            const float* wr = eW_ih1 + j0 * LL;
            const float* wz = eW_ih1 + (200 + j0) * LL;
            const float* wn = eW_ih1 + (400 + j0) * LL;
            #pragma unroll 1
            for (int k = 0; k < LL; k += 2) {
                float4 u = *(const float4*)(h1s + k * 32 + b0);
                float4 w = *(const float4*)(h1s + (k + 1) * 32 + b0);
                float va[4] = {u.x, u.y, u.z, u.w};
                float vb[4] = {w.x, w.y, w.z, w.w};
                #pragma unroll
                for (int jj = 0; jj < 2; jj++) {
                    float2 a = *(const float2*)(wr + jj * LL + k);
                    float2 c = *(const float2*)(wz + jj * LL + k);
                    float2 d = *(const float2*)(wn + jj * LL + k);
                    #pragma unroll
                    for (int bb = 0; bb < 4; bb++) {
                        ar[jj][bb] = fmaf(a.x, va[bb], ar[jj][bb]);
                        ar[jj][bb] = fmaf(a.y, vb[bb], ar[jj][bb]);
                        az[jj][bb] = fmaf(c.x, va[bb], az[jj][bb]);
                        az[jj][bb] = fmaf(c.y, vb[bb], az[jj][bb]);
                        an[jj][bb] = fmaf(d.x, va[bb], an[jj][bb]);
                        an[jj][bb] = fmaf(d.y, vb[bb], an[jj][bb]);
                    }
                }
            }
        }
        {   // hh part over h2 (r, z, n_hidden)
            const float* wr = eW_hh1 + j0 * LL;
            const float* wz = eW_hh1 + (200 + j0) * LL;
            const float* wn = eW_hh1 + (400 + j0) * LL;
            #pragma unroll 1
            for (int k = 0; k < LL; k += 2) {
                float4 u = *(const float4*)(h2s + k * 32 + b0);
                float4 w = *(const float4*)(h2s + (k + 1) * 32 + b0);
                float va[4] = {u.x, u.y, u.z, u.w};
                float vb[4] = {w.x, w.y, w.z, w.w};
                #pragma unroll
                for (int jj = 0; jj < 2; jj++) {
                    float2 a = *(const float2*)(wr + jj * LL + k);
                    float2 c = *(const float2*)(wz + jj * LL + k);
                    float2 d = *(const float2*)(wn + jj * LL + k);
                    #pragma unroll
                    for (int bb = 0; bb < 4; bb++) {
                        ar[jj][bb] = fmaf(a.x, va[bb], ar[jj][bb]);
                        ar[jj][bb] = fmaf(a.y, vb[bb], ar[jj][bb]);
                        az[jj][bb] = fmaf(c.x, va[bb], az[jj][bb]);
                        az[jj][bb] = fmaf(c.y, vb[bb], az[jj][bb]);
                        ah[jj][bb] = fmaf(d.x, va[bb], ah[jj][bb]);
                        ah[jj][bb] = fmaf(d.y, vb[bb], ah[jj][bb]);
                    }
                }
            }
        }
        __syncthreads();
        #pragma unroll
        for (int jj = 0; jj < 2; jj++)
            #pragma unroll
            for (int bb = 0; bb < 4; bb++) {
                int idx = (j0 + jj) * 32 + b0 + bb;
                float ho = h2s[idx];
                float r  = sigm(ar[jj][bb]);
                float zg = sigm(az[jj][bb]);
                float n  = tanhf(fmaf(r, ah[jj][bb], an[jj][bb]));
                h2s[idx] = (1.0f - zg) * n + zg * ho;
            }
        __syncthreads();
    }

    // =====================  HEADS: mu, logvar, z, predY  =====================
    {
        float am[2][4], al[2][4];
        #pragma unroll
        for (int jj = 0; jj < 2; jj++) {
            float bm = fc11_b[j0 + jj], bl = fc12_b[j0 + jj];
            #pragma unroll
            for (int bb = 0; bb < 4; bb++) { am[jj][bb] = bm; al[jj][bb] = bl; }
        }
        const float* w1 = fc11_w + j0 * LL;
        const float* w2 = fc12_w + j0 * LL;
        #pragma unroll 1
        for (int k = 0; k < LL; k += 2) {
            float4 u = *(const float4*)(h2s + k * 32 + b0);
            float4 w = *(const float4*)(h2s + (k + 1) * 32 + b0);
            float va[4] = {u.x, u.y, u.z, u.w};
            float vb[4] = {w.x, w.y, w.z, w.w};
            #pragma unroll
            for (int jj = 0; jj < 2; jj++) {
                float2 a = *(const float2*)(w1 + jj * LL + k);
                float2 c = *(const float2*)(w2 + jj * LL + k);
                #pragma unroll
                for (int bb = 0; bb < 4; bb++) {
                    am[jj][bb] = fmaf(a.x, va[bb], am[jj][bb]);
                    am[jj][bb] = fmaf(a.y, vb[bb], am[jj][bb]);
                    al[jj][bb] = fmaf(c.x, va[bb], al[jj][bb]);
                    al[jj][bb] = fmaf(c.y, vb[bb], al[jj][bb]);
                }
            }
        }
        #pragma unroll
        for (int jj = 0; jj < 2; jj++)
            #pragma unroll
            for (int bb = 0; bb < 4; bb++) {
                int j = j0 + jj, b = b0 + bb, bg = bg0 + b;
                float m = am[jj][bb], lv = al[jj][bb];
                out[MU_OFF + (size_t)bg * LL + j] = m;
                out[LV_OFF + (size_t)bg * LL + j] = lv;
                mus[j * 32 + b] = m;
                zs[j * 32 + b] = fmaf(eps[(size_t)bg * LL + j], expf(0.5f * lv), m);
            }
        __syncthreads();
    }
    {   // t1 = relu(mu @ p1^T + p1_b) -> overwrite h2s (no longer needed)
        float aa[2][4];
        #pragma unroll
        for (int jj = 0; jj < 2; jj++) {
            float bv = p1_b[j0 + jj];
            #pragma unroll
            for (int bb = 0; bb < 4; bb++) aa[jj][bb] = bv;
        }
        const float* w1 = p1_w + j0 * LL;
        #pragma unroll 1
        for (int k = 0; k < LL; k += 2) {
            float4 u = *(const float4*)(mus + k * 32 + b0);
            float4 w = *(const float4*)(mus + (k + 1) * 32 + b0);
            float va[4] = {u.x, u.y, u.z, u.w};
            float vb[4] = {w.x, w.y, w.z, w.w};
            #pragma unroll
            for (int jj = 0; jj < 2; jj++) {
                float2 a = *(const float2*)(w1 + jj * LL + k);
                #pragma unroll
                for (int bb = 0; bb < 4; bb++) {
                    aa[jj][bb] = fmaf(a.x, va[bb], aa[jj][bb]);
                    aa[jj][bb] = fmaf(a.y, vb[bb], aa[jj][bb]);
                }
            }
        }
        #pragma unroll
        for (int jj = 0; jj < 2; jj++)
            #pragma unroll
            for (int bb = 0; bb < 4; bb++)
                h2s[(j0 + jj) * 32 + b0 + bb] = fmaxf(aa[jj][bb], 0.0f);
        __syncthreads();
    }
    // predY (one thread per batch row)
    if (tid < 32) {
        float a = p2_b[0];
        for (int j = 0; j < LL; j++) a = fmaf(p2_w[j], h2s[j * 32 + tid], a);
        out[PY_OFF + bg0 + tid] = a;
    }
    // gz = z @ dW_ih0[:, :L]^T + db_ih0  (constant across decode steps)
    for (int idx = tid; idx < GE3 * 32; idx += NTH) {
        int g = idx >> 5, b = idx & 31;
        float a = db_ih0[g];
        const float* w = dW_ih0 + g * LE;
        #pragma unroll 4
        for (int k = 0; k < LL; k++) a = fmaf(zs[k * 32 + b], w[k], a);
        gzs[idx] = a;
    }
    // clear lastword
    for (int i = tid; i < EE * 32; i += NTH) xes[i] = 0.0f;
    __syncthreads();

    // =====================  DECODER (zero-hidden GRUs + fc2)  =====================
    for (int t = 0; t < TT; t++) {
        // gi1 = gz + lastword @ dW_ih0[:, L:]^T
        for (int idx = tid; idx < GE3 * 32; idx += NTH) {
            int g = idx >> 5, b = idx & 31;
            float a = gzs[idx];
            const float* w = dW_ih0 + g * LE + LL;
            #pragma unroll 5
            for (int k = 0; k < EE; k++) a = fmaf(xes[k * 32 + b], w[k], a);
            g1s[idx] = a;
        }
        __syncthreads();
        // h1 = (1-z)*tanh(gi_n + sig(gi_r + bhh_r)*bhh_n)   (gh == bhh since h==0)
        for (int idx = tid; idx < EE * 32; idx += NTH) {
            int e = idx >> 5, b = idx & 31;
            float r  = sigm(g1s[e * 32 + b] + db_hh0[e]);
            float zg = sigm(g1s[(EE + e) * 32 + b] + db_hh0[EE + e]);
            float n  = tanhf(fmaf(r, db_hh0[2 * EE + e], g1s[(2 * EE + e) * 32 + b]));
            hds[idx] = (1.0f - zg) * n;
        }
        __syncthreads();
        // gi2 = h1 @ dW_ih1^T + db_ih1 (reuse g1s)
        for (int idx = tid; idx < GE3 * 32; idx += NTH) {
            int g = idx >> 5, b = idx & 31;
            float a = db_ih1[g];
            const float* w = dW_ih1 + g * EE;
            #pragma unroll 5
            for (int k = 0; k < EE; k++) a = fmaf(hds[k * 32 + b], w[k], a);
            g1s[idx] = a;
        }
        __syncthreads();
        // h2 = output word -> becomes lastword (xes)
        for (int idx = tid; idx < EE * 32; idx += NTH) {
            int e = idx >> 5, b = idx & 31;
            float r  = sigm(g1s[e * 32 + b] + db_hh1[e]);
            float zg = sigm(g1s[(EE + e) * 32 + b] + db_hh1[EE + e]);
            float n  = tanhf(fmaf(r, db_hh1[2 * EE + e], g1s[(2 * EE + e) * 32 + b]));
            xes[idx] = (1.0f - zg) * n;
        }
        __syncthreads();
        // pred[:, t, :] = h2 @ fc2_w^T + fc2_b
        for (int idx = tid; idx < KV * 32; idx += NTH) {
            int kk = idx >> 5, b = idx & 31;
            float a = fc2_b[kk];
            const float* w = fc2_w + kk * EE;
            #pragma unroll 5
            for (int e = 0; e < EE; e++) a = fmaf(xes[e * 32 + b], w[e], a);
            out[PRED_OFF + ((size_t)(bg0 + b) * TT + t) * KV + kk] = a;
        }
        __syncthreads();
    }
}

extern "C" void kernel_launch(void* const* d_in, const int* in_sizes, int n_in,
                              void* d_out, int out_size) {
    (void)in_sizes; (void)n_in; (void)out_size;
    const int*   x       = (const int*)  d_in[0];
    const float* emb     = (const float*)d_in[1];
    const float* eW_ih0  = (const float*)d_in[2];
    const float* eW_hh0  = (const float*)d_in[3];
    const float* eb_ih0  = (const float*)d_in[4];
    const float* eb_hh0  = (const float*)d_in[5];
    const float* eW_ih1  = (const float*)d_in[6];
    const float* eW_hh1  = (const float*)d_in[7];
    const float* eb_ih1  = (const float*)d_in[8];
    const float* eb_hh1  = (const float*)d_in[9];
    const float* dW_ih0  = (const float*)d_in[10];
    // d_in[11] = dW_hh0: unused (decoder hidden state is always zero)
    const float* db_ih0  = (const float*)d_in[12];
    const float* db_hh0  = (const float*)d_in[13];
    const float* dW_ih1  = (const float*)d_in[14];
    // d_in[15] = dW_hh1: unused
    const float* db_ih1  = (const float*)d_in[16];
    const float* db_hh1  = (const float*)d_in[17];
    const float* fc11_w  = (const float*)d_in[18];
    const float* fc11_b  = (const float*)d_in[19];
    const float* fc12_w  = (const float*)d_in[20];
    const float* fc12_b  = (const float*)d_in[21];
    const float* p1_w    = (const float*)d_in[22];
    const float* p1_b    = (const float*)d_in[23];
    const float* p2_w    = (const float*)d_in[24];
    const float* p2_b    = (const float*)d_in[25];
    const float* fc2_w   = (const float*)d_in[26];
    const float* fc2_b   = (const float*)d_in[27];
    const float* eps     = (const float*)d_in[28];

    cudaFuncSetAttribute((const void*)vae_all,
                         cudaFuncAttributeMaxDynamicSharedMemorySize,
                         SMEM_FLOATS * (int)sizeof(float));

    vae_all<<<NCTA, NTH, SMEM_FLOATS * sizeof(float)>>>(
        x, emb, eW_ih0, eW_hh0, eb_ih0, eb_hh0, eW_ih1, eW_hh1, eb_ih1, eb_hh1,
        dW_ih0, db_ih0, db_hh0, dW_ih1, db_ih1, db_hh1,
        fc11_w, fc11_b, fc12_w, fc12_b, p1_w, p1_b, p2_w, p2_b,
        fc2_w, fc2_b, eps, (float*)d_out);
}